// round 14
// baseline (speedup 1.0000x reference)
#include <cuda_runtime.h>
#include <math.h>
#include <stdint.h>

// Kalman filter one-step-ahead predictions. B=512, T=256, S=32, M=4.
// Warp-per-batch (32x512). Tensor-pipe covariance propagation:
//   Yt = F*P (MMA1, overlaps innovation);  P' = F*Y + Q - W*W^T (MMA2)
// R14: PH^T is pipelined across the step boundary via
//   pht(t+1) = (HF)*Yt_rows + HQ - (HW)*W,  HW = (HF)*Z
// computed in MMA2's shadow; per-lane p column and its reload are deleted.

#define Bn 512
#define Tn 256
#define Sn 32
#define Mn 4
#define PL 37   // fp32 plane stride (conflict-free)

using u64 = unsigned long long;

__device__ __forceinline__ u64 pack2(float lo, float hi) {
    u64 r; asm("mov.b64 %0,{%1,%2};" : "=l"(r) : "f"(lo), "f"(hi)); return r;
}
__device__ __forceinline__ void unpack2(u64 v, float& lo, float& hi) {
    asm("mov.b64 {%0,%1},%2;" : "=f"(lo), "=f"(hi) : "l"(v));
}
__device__ __forceinline__ u64 ffma2(u64 a, u64 b, u64 c) {
    u64 d; asm("fma.rn.f32x2 %0,%1,%2,%3;" : "=l"(d) : "l"(a), "l"(b), "l"(c)); return d;
}
__device__ __forceinline__ u64 fadd2(u64 a, u64 b) {
    u64 d; asm("add.rn.f32x2 %0,%1,%2;" : "=l"(d) : "l"(a), "l"(b)); return d;
}
__device__ __forceinline__ void split_tf32(float x, uint32_t& h, uint32_t& l) {
    h = __float_as_uint(x) & 0xffffe000u;
    float r = x - __uint_as_float(h);
    l = __float_as_uint(r) & 0xffffe000u;
}
__device__ __forceinline__ void mma_tf32(float* c, const uint32_t* a,
                                         uint32_t b0, uint32_t b1) {
    asm volatile(
        "mma.sync.aligned.m16n8k8.row.col.f32.tf32.tf32.f32 "
        "{%0,%1,%2,%3},{%4,%5,%6,%7},{%8,%9},{%0,%1,%2,%3};"
        : "+f"(c[0]), "+f"(c[1]), "+f"(c[2]), "+f"(c[3])
        : "r"(a[0]), "r"(a[1]), "r"(a[2]), "r"(a[3]), "r"(b0), "r"(b1));
}

__global__ __launch_bounds__(32) void kalman_kernel(
    const float* __restrict__ obs,       // [B,T,M]
    const float* __restrict__ Fm,        // [S,S]
    const float* __restrict__ Qm,        // [S,S]
    const float* __restrict__ Hm,        // [M,S]
    const float* __restrict__ Rm,        // [M,M]
    const float* __restrict__ init_mean, // [B,S]
    const float* __restrict__ init_cov,  // [B,S,S]
    float* __restrict__ out)
{
    const int b    = blockIdx.x;
    const int lane = threadIdx.x;
    const int g    = lane >> 2;
    const int tg   = lane & 3;

    __shared__ __align__(16) u64 sHTp[Sn * 2];   // [l*4+q] = H[q][l] (prime)
    __shared__ __align__(16) u64 sHR[4 * 17];    // hr[q*34+l] = H[q][l]
    __shared__ __align__(16) u64 sFR[Sn * 17];   // fr[j*34+l] = F[j][l]
    __shared__ __align__(16) u64 sHFq[Sn * 2];   // [k*4+r] = (HF)[r][k]
    __shared__ __align__(16) u64 sPHT[4 * 17];   // pht[r*34+l]
    __shared__ __align__(16) float sHQ[4 * 33];  // HQ[r][l] at [r*33+l]
    __shared__ __align__(16) float sHWm[16];     // HW 4x4 (row-major)
    __shared__ __align__(16) float sZ[Sn * 4];   // whitened z rows
    __shared__ __align__(16) float sW[Sn * 4];   // W = F*Z rows
    __shared__ __align__(16) u64 sMu[16];
    __shared__ __align__(16) u64 sMp[16];
    __shared__ float sR16[16];
    __shared__ float sQf[32 * 33];               // Q acc-layout fragments
    __shared__ float sPu[Sn * PL];               // P plane (persistent)
    __shared__ float sXt[Sn * PL];               // Yt = F*P plane

    {
        float* frf = (float*)sFR;
        for (int idx = lane; idx < Sn * Sn; idx += 32) {
            int i = idx >> 5, l = idx & 31;
            frf[i * 34 + l] = Fm[idx];
        }
        float* hv  = (float*)sHTp;
        float* hrf = (float*)sHR;
        for (int idx = lane; idx < Mn * Sn; idx += 32) {
            int q = idx >> 5, l = idx & 31;
            float h = Hm[idx];
            hv [l * 4 + q]  = h;
            hrf[q * 34 + l] = h;
        }
        if (lane < 16) sR16[lane] = Rm[lane];
        for (int ti = 0; ti < 8; ++ti) {
            int mt = ti >> 2, nt = ti & 3;
#pragma unroll
            for (int j = 0; j < 4; ++j) {
                int row = mt * 16 + g + 8 * (j >> 1);
                int col = nt * 8 + 2 * tg + (j & 1);
                sQf[(ti * 4 + j) * 33 + lane] = Qm[row * Sn + col];
            }
        }
        // HF[r][k] and HQ[r][l] constants (k = l = lane)
        float* hfv = (float*)sHFq;
#pragma unroll
        for (int r = 0; r < 4; ++r) {
            float af = 0.f, aq = 0.f;
            for (int j = 0; j < Sn; ++j) {
                float h = Hm[r * Sn + j];
                af = fmaf(h, Fm[j * Sn + lane], af);
                aq = fmaf(h, Qm[j * Sn + lane], aq);
            }
            hfv[lane * 4 + r] = af;
            sHQ[r * 33 + lane] = aq;
        }
    }

    // ---- constant F A-fragments, hi+lo mask split ----
    uint32_t fh[8][4], fl[8][4];
#pragma unroll
    for (int mt = 0; mt < 2; ++mt)
#pragma unroll
        for (int kt = 0; kt < 4; ++kt) {
            int r0 = mt * 16 + g, c0 = kt * 8 + tg;
            float v[4];
            v[0] = Fm[r0 * Sn + c0];
            v[1] = Fm[(r0 + 8) * Sn + c0];
            v[2] = Fm[r0 * Sn + c0 + 4];
            v[3] = Fm[(r0 + 8) * Sn + c0 + 4];
#pragma unroll
            for (int j = 0; j < 4; ++j)
                split_tf32(v[j], fh[mt * 4 + kt][j], fl[mt * 4 + kt][j]);
        }

    float mloc = init_mean[b * Sn + lane];
    float* muF = (float*)sMu;
    float* mpF = (float*)sMp;
    mpF[lane] = mloc;
    float* phtF = (float*)sPHT;

    // ---- prime: P(0) plane + pht(0) = rows of P0*H^T ----
    float ph0, ph1, phh2, ph3;
    {
        float pc[Sn];
#pragma unroll
        for (int i = 0; i < Sn; ++i) {
            pc[i] = init_cov[(size_t)b * (Sn * Sn) + i * Sn + lane];
            sPu[i * PL + lane] = pc[i];
        }
        __syncwarp();
        u64 a00 = 0ull, a01 = 0ull, a10 = 0ull, a11 = 0ull;
#pragma unroll
        for (int l = 0; l < Sn; l += 2) {
            ulonglong2 h0 = *(const ulonglong2*)&sHTp[l * 2];
            ulonglong2 h1 = *(const ulonglong2*)&sHTp[(l + 1) * 2];
            u64 ps0 = pack2(pc[l], pc[l]);
            u64 ps1 = pack2(pc[l + 1], pc[l + 1]);
            a00 = ffma2(ps0, h0.x, a00); a10 = ffma2(ps0, h0.y, a10);
            a01 = ffma2(ps1, h1.x, a01); a11 = ffma2(ps1, h1.y, a11);
        }
        u64 ph2a = fadd2(a00, a01);
        u64 ph2b = fadd2(a10, a11);
        unpack2(ph2a, ph0, ph1);
        unpack2(ph2b, phh2, ph3);
        phtF[0 * 34 + lane] = ph0;
        phtF[1 * 34 + lane] = ph1;
        phtF[2 * 34 + lane] = phh2;
        phtF[3 * 34 + lane] = ph3;
    }
    __syncwarp();

    const float* yb = obs + (size_t)b * (Tn * Mn);
    float* out_means = out;
    float* out_covs  = out + (size_t)Tn * Bn * Mn;

    float4 yn = *(const float4*)yb;

#pragma unroll 1
    for (int t = 0; t < Tn; ++t) {
        float4 yv = yn;
        int tnext = (t + 1 < Tn) ? (t + 1) : (Tn - 1);
        yn = *(const float4*)(yb + 4 * tnext);

        // ======== MMA1: Yt = F * P (independent of innovation) ========
        float yac[8][4];
#pragma unroll
        for (int ti = 0; ti < 8; ++ti)
#pragma unroll
            for (int j = 0; j < 4; ++j) yac[ti][j] = 0.f;
#pragma unroll
        for (int kt = 0; kt < 4; ++kt) {
#pragma unroll
            for (int nt = 0; nt < 4; ++nt) {
                float rb0 = sPu[(kt * 8 + tg) * PL + nt * 8 + g];
                float rb1 = sPu[(kt * 8 + tg + 4) * PL + nt * 8 + g];
                uint32_t bh0, bl0, bh1, bl1;
                split_tf32(rb0, bh0, bl0);
                split_tf32(rb1, bh1, bl1);
#pragma unroll
                for (int mt = 0; mt < 2; ++mt) {
                    mma_tf32(yac[mt * 4 + nt], fh[mt * 4 + kt], bh0, bh1);
                    mma_tf32(yac[mt * 4 + nt], fh[mt * 4 + kt], bl0, bl1);
                    mma_tf32(yac[mt * 4 + nt], fl[mt * 4 + kt], bh0, bh1);
                }
            }
        }
#pragma unroll
        for (int ti = 0; ti < 8; ++ti) {
            int mt = ti >> 2, nt = ti & 3;
            int rr = mt * 16 + g, cc = nt * 8 + 2 * tg;
            sXt[rr * PL + cc]           = yac[ti][0];
            sXt[rr * PL + cc + 1]       = yac[ti][1];
            sXt[(rr + 8) * PL + cc]     = yac[ti][2];
            sXt[(rr + 8) * PL + cc + 1] = yac[ti][3];
        }

        // ======== innovation head (pht already in regs/sPHT) ========
        float mmv = 0.f;
        {
            u64 accm0 = 0ull, accm1 = 0ull;
            const u64* hq = &sHR[(lane & 3) * 17];
#pragma unroll
            for (int c = 0; c < 8; ++c) {
                accm0 = ffma2(hq[2 * c + 0], sMp[2 * c + 0], accm0);
                accm1 = ffma2(hq[2 * c + 1], sMp[2 * c + 1], accm1);
            }
            u64 accm = fadd2(accm0, accm1);
            float alo, ahi; unpack2(accm, alo, ahi);
            mmv = alo + ahi;
        }
        float c0 = __shfl_sync(0xffffffffu, mmv, 0);
        float c1 = __shfl_sync(0xffffffffu, mmv, 1);
        float c2 = __shfl_sync(0xffffffffu, mmv, 2);
        float c3 = __shfl_sync(0xffffffffu, mmv, 3);
        if (lane == 0)
            *(float4*)&out_means[((size_t)t * Bn + b) * 4] = make_float4(c0, c1, c2, c3);
        float r0 = yv.x - c0, r1 = yv.y - c1, r2 = yv.z - c2, r3 = yv.w - c3;

        // S = H*(PH^T) + R  (from sPHT, stored last tail / prime)
        int q = (lane >> 2) & 3, r = lane & 3;
        float sv;
        {
            u64 acc0 = 0ull, acc1 = 0ull;
            const u64* hq = &sHR [q * 17];
            const u64* pr = &sPHT[r * 17];
#pragma unroll
            for (int c = 0; c < 8; ++c) {
                acc0 = ffma2(hq[2 * c + 0], pr[2 * c + 0], acc0);
                acc1 = ffma2(hq[2 * c + 1], pr[2 * c + 1], acc1);
            }
            u64 acc = fadd2(acc0, acc1);
            float alo, ahi; unpack2(acc, alo, ahi);
            sv = sR16[(q << 2) | r] + (alo + ahi);
        }
        if (lane < 16)
            out_covs[((size_t)t * Bn + b) * 16 + lane] = sv;

        if (t == Tn - 1) break;

        float s00 = __shfl_sync(0xffffffffu, sv, 0);
        float s10 = __shfl_sync(0xffffffffu, sv, 4);
        float s11 = __shfl_sync(0xffffffffu, sv, 5);
        float s20 = __shfl_sync(0xffffffffu, sv, 8);
        float s21 = __shfl_sync(0xffffffffu, sv, 9);
        float s22 = __shfl_sync(0xffffffffu, sv, 10);
        float s30 = __shfl_sync(0xffffffffu, sv, 12);
        float s31 = __shfl_sync(0xffffffffu, sv, 13);
        float s32 = __shfl_sync(0xffffffffu, sv, 14);
        float s33 = __shfl_sync(0xffffffffu, sv, 15);
        float i0 = rsqrtf(s00);
        float L10 = s10 * i0, L20 = s20 * i0, L30 = s30 * i0;
        float i1 = rsqrtf(s11 - L10 * L10);
        float L21 = (s21 - L20 * L10) * i1;
        float L31 = (s31 - L30 * L10) * i1;
        float i2 = rsqrtf(s22 - L20 * L20 - L21 * L21);
        float L32 = (s32 - L30 * L20 - L31 * L21) * i2;
        float i3 = rsqrtf(s33 - L30 * L30 - L31 * L31 - L32 * L32);

        float z0 = ph0 * i0;
        float z1 = (ph1 - L10 * z0) * i1;
        float z2 = (phh2 - L20 * z0 - L21 * z1) * i2;
        float z3 = (ph3 - L30 * z0 - L31 * z1 - L32 * z2) * i3;
        float k3 = z3 * i3;
        float k2 = (z2 - L32 * k3) * i2;
        float k1 = (z1 - L21 * k2 - L31 * k3) * i1;
        float k0 = (z0 - L10 * k1 - L20 * k2 - L30 * k3) * i0;

        *(float4*)&sZ[lane * 4] = make_float4(z0, z1, z2, z3);
        __syncwarp();

        mloc = fmaf(k0, r0, fmaf(k1, r1, fmaf(k2, r2, fmaf(k3, r3, mloc))));
        muF[lane] = mloc;

        // ---- W = F * Z  and  HW = (HF) * Z  (independent chains) ----
        float w0 = 0.f, w1 = 0.f, w2 = 0.f, w3 = 0.f;
        {
            const u64* frw = &sFR[lane * 17];
#pragma unroll
            for (int c = 0; c < 16; ++c) {
                float f0, f1; unpack2(frw[c], f0, f1);
                float4 za = *(const float4*)&sZ[(2 * c) * 4];
                float4 zb = *(const float4*)&sZ[(2 * c + 1) * 4];
                w0 = fmaf(f0, za.x, w0); w1 = fmaf(f0, za.y, w1);
                w2 = fmaf(f0, za.z, w2); w3 = fmaf(f0, za.w, w3);
                w0 = fmaf(f1, zb.x, w0); w1 = fmaf(f1, zb.y, w1);
                w2 = fmaf(f1, zb.z, w2); w3 = fmaf(f1, zb.w, w3);
            }
        }
        *(float4*)&sW[lane * 4] = make_float4(w0, w1, w2, w3);
        {
            // HW[q][c] = sum_k HF[q][k] * Z[k][c]; all lanes (dup >=16)
            const float* hfv = (const float*)sHFq;
            float hacc0 = 0.f, hacc1 = 0.f;
#pragma unroll
            for (int k = 0; k < Sn; k += 2) {
                hacc0 = fmaf(hfv[k * 4 + q], sZ[k * 4 + r], hacc0);
                hacc1 = fmaf(hfv[(k + 1) * 4 + q], sZ[(k + 1) * 4 + r], hacc1);
            }
            if (lane < 16) sHWm[(q << 2) | r] = hacc0 + hacc1;
        }
        __syncwarp();   // sW, sHWm, sXt, sMu visible

        // ---- pht(t+1) = (HF)*Yt_row + HQ - HW*w  (MMA2 shadow) ----
        {
            u64 aA0 = 0ull, aA1 = 0ull, aB0 = 0ull, aB1 = 0ull;
            const float* yrow = &sXt[lane * PL];
#pragma unroll
            for (int k = 0; k < Sn; k += 2) {
                float y0 = yrow[k], y1 = yrow[k + 1];
                u64 p0 = pack2(y0, y0), p1 = pack2(y1, y1);
                ulonglong2 h0 = *(const ulonglong2*)&sHFq[k * 2];
                ulonglong2 h1 = *(const ulonglong2*)&sHFq[(k + 1) * 2];
                aA0 = ffma2(p0, h0.x, aA0); aB0 = ffma2(p0, h0.y, aB0);
                aA1 = ffma2(p1, h1.x, aA1); aB1 = ffma2(p1, h1.y, aB1);
            }
            u64 pa = fadd2(aA0, aA1);
            u64 pb = fadd2(aB0, aB1);
            unpack2(pa, ph0, ph1);
            unpack2(pb, phh2, ph3);
            float4 hw0 = *(const float4*)&sHWm[0];
            float4 hw1 = *(const float4*)&sHWm[4];
            float4 hw2 = *(const float4*)&sHWm[8];
            float4 hw3 = *(const float4*)&sHWm[12];
            ph0 += sHQ[0 * 33 + lane]
                 - (hw0.x * w0 + hw0.y * w1 + hw0.z * w2 + hw0.w * w3);
            ph1 += sHQ[1 * 33 + lane]
                 - (hw1.x * w0 + hw1.y * w1 + hw1.z * w2 + hw1.w * w3);
            phh2 += sHQ[2 * 33 + lane]
                 - (hw2.x * w0 + hw2.y * w1 + hw2.z * w2 + hw2.w * w3);
            ph3 += sHQ[3 * 33 + lane]
                 - (hw3.x * w0 + hw3.y * w1 + hw3.z * w2 + hw3.w * w3);
            phtF[0 * 34 + lane] = ph0;
            phtF[1 * 34 + lane] = ph1;
            phtF[2 * 34 + lane] = phh2;
            phtF[3 * 34 + lane] = ph3;
        }

        // ---- mean predict ----
        float mp;
        {
            u64 acc0 = 0ull, acc1 = 0ull;
            const u64* frw = &sFR[lane * 17];
#pragma unroll
            for (int c = 0; c < 8; ++c) {
                acc0 = ffma2(frw[2 * c + 0], sMu[2 * c + 0], acc0);
                acc1 = ffma2(frw[2 * c + 1], sMu[2 * c + 1], acc1);
            }
            u64 acc = fadd2(acc0, acc1);
            float alo, ahi; unpack2(acc, alo, ahi);
            mp = alo + ahi;
        }

        // ======== MMA2: P' = F * Y + Q, Y[k][n] = Yt[n][k] ========
        float pac[8][4];
#pragma unroll
        for (int ti = 0; ti < 8; ++ti)
#pragma unroll
            for (int j = 0; j < 4; ++j)
                pac[ti][j] = sQf[(ti * 4 + j) * 33 + lane];
#pragma unroll
        for (int kt = 0; kt < 4; ++kt) {
#pragma unroll
            for (int nt = 0; nt < 4; ++nt) {
                float rb0 = sXt[(nt * 8 + g) * PL + kt * 8 + tg];
                float rb1 = sXt[(nt * 8 + g) * PL + kt * 8 + tg + 4];
                uint32_t bh0, bl0, bh1, bl1;
                split_tf32(rb0, bh0, bl0);
                split_tf32(rb1, bh1, bl1);
#pragma unroll
                for (int mt = 0; mt < 2; ++mt) {
                    mma_tf32(pac[mt * 4 + nt], fh[mt * 4 + kt], bh0, bh1);
                    mma_tf32(pac[mt * 4 + nt], fh[mt * 4 + kt], bl0, bl1);
                    mma_tf32(pac[mt * 4 + nt], fl[mt * 4 + kt], bh0, bh1);
                }
            }
        }

        // ---- rank-4 correction on fragments: pac -= W_row . W_col ----
#pragma unroll
        for (int ti = 0; ti < 8; ++ti) {
            int mt = ti >> 2, nt = ti & 3;
            int rr = mt * 16 + g, cc = nt * 8 + 2 * tg;
            float4 wr0 = *(const float4*)&sW[rr * 4];
            float4 wr1 = *(const float4*)&sW[(rr + 8) * 4];
            float4 wc0 = *(const float4*)&sW[cc * 4];
            float4 wc1 = *(const float4*)&sW[(cc + 1) * 4];
            float d00 = wr0.x * wc0.x; d00 = fmaf(wr0.y, wc0.y, d00);
            d00 = fmaf(wr0.z, wc0.z, d00); d00 = fmaf(wr0.w, wc0.w, d00);
            float d01 = wr0.x * wc1.x; d01 = fmaf(wr0.y, wc1.y, d01);
            d01 = fmaf(wr0.z, wc1.z, d01); d01 = fmaf(wr0.w, wc1.w, d01);
            float d10 = wr1.x * wc0.x; d10 = fmaf(wr1.y, wc0.y, d10);
            d10 = fmaf(wr1.z, wc0.z, d10); d10 = fmaf(wr1.w, wc0.w, d10);
            float d11 = wr1.x * wc1.x; d11 = fmaf(wr1.y, wc1.y, d11);
            d11 = fmaf(wr1.z, wc1.z, d11); d11 = fmaf(wr1.w, wc1.w, d11);
            pac[ti][0] -= d00;
            pac[ti][1] -= d01;
            pac[ti][2] -= d10;
            pac[ti][3] -= d11;
        }

        // store P' plane
#pragma unroll
        for (int ti = 0; ti < 8; ++ti) {
            int mt = ti >> 2, nt = ti & 3;
            int rr = mt * 16 + g, cc = nt * 8 + 2 * tg;
            sPu[rr * PL + cc]           = pac[ti][0];
            sPu[rr * PL + cc + 1]       = pac[ti][1];
            sPu[(rr + 8) * PL + cc]     = pac[ti][2];
            sPu[(rr + 8) * PL + cc + 1] = pac[ti][3];
        }

        mloc = mp;
        mpF[lane] = mp;
        __syncwarp();
    }
}

extern "C" void kernel_launch(void* const* d_in, const int* in_sizes, int n_in,
                              void* d_out, int out_size)
{
    const float* obs       = (const float*)d_in[0];
    const float* Fm        = (const float*)d_in[1];
    const float* Qm        = (const float*)d_in[2];
    const float* Hm        = (const float*)d_in[3];
    const float* Rm        = (const float*)d_in[4];
    const float* init_mean = (const float*)d_in[5];
    const float* init_cov  = (const float*)d_in[6];
    float* out = (float*)d_out;

    kalman_kernel<<<Bn, 32>>>(obs, Fm, Qm, Hm, Rm, init_mean, init_cov, out);
}

// round 15
// speedup vs baseline: 1.1044x; 1.1044x over previous
#include <cuda_runtime.h>
#include <math.h>
#include <stdint.h>

// Kalman filter one-step-ahead predictions. B=512, T=256, S=32, M=4.
// Warp-per-batch (32x512). Tensor-pipe covariance propagation:
//   Yt = F*P   (MMA1, independent of innovation -> overlaps it)
//   P' = F*Y + Q - W*W^T,  W = F*Z   (MMA2 + fragment rank-4 correction)
// R15 = R13 + back-solve elimination: u = L^-1*resid (broadcast scalars),
// m_u = m + Z*u  — deletes the per-lane K back-solve from the serial chain.

#define Bn 512
#define Tn 256
#define Sn 32
#define Mn 4
#define PL 37   // fp32 plane stride (conflict-free)

using u64 = unsigned long long;

__device__ __forceinline__ u64 pack2(float lo, float hi) {
    u64 r; asm("mov.b64 %0,{%1,%2};" : "=l"(r) : "f"(lo), "f"(hi)); return r;
}
__device__ __forceinline__ void unpack2(u64 v, float& lo, float& hi) {
    asm("mov.b64 {%0,%1},%2;" : "=f"(lo), "=f"(hi) : "l"(v));
}
__device__ __forceinline__ u64 ffma2(u64 a, u64 b, u64 c) {
    u64 d; asm("fma.rn.f32x2 %0,%1,%2,%3;" : "=l"(d) : "l"(a), "l"(b), "l"(c)); return d;
}
__device__ __forceinline__ u64 fadd2(u64 a, u64 b) {
    u64 d; asm("add.rn.f32x2 %0,%1,%2;" : "=l"(d) : "l"(a), "l"(b)); return d;
}
__device__ __forceinline__ void split_tf32(float x, uint32_t& h, uint32_t& l) {
    h = __float_as_uint(x) & 0xffffe000u;
    float r = x - __uint_as_float(h);
    l = __float_as_uint(r) & 0xffffe000u;
}
__device__ __forceinline__ void mma_tf32(float* c, const uint32_t* a,
                                         uint32_t b0, uint32_t b1) {
    asm volatile(
        "mma.sync.aligned.m16n8k8.row.col.f32.tf32.tf32.f32 "
        "{%0,%1,%2,%3},{%4,%5,%6,%7},{%8,%9},{%0,%1,%2,%3};"
        : "+f"(c[0]), "+f"(c[1]), "+f"(c[2]), "+f"(c[3])
        : "r"(a[0]), "r"(a[1]), "r"(a[2]), "r"(a[3]), "r"(b0), "r"(b1));
}

__global__ __launch_bounds__(32) void kalman_kernel(
    const float* __restrict__ obs,       // [B,T,M]
    const float* __restrict__ Fm,        // [S,S]
    const float* __restrict__ Qm,        // [S,S]
    const float* __restrict__ Hm,        // [M,S]
    const float* __restrict__ Rm,        // [M,M]
    const float* __restrict__ init_mean, // [B,S]
    const float* __restrict__ init_cov,  // [B,S,S]
    float* __restrict__ out)
{
    const int b    = blockIdx.x;
    const int lane = threadIdx.x;
    const int g    = lane >> 2;
    const int tg   = lane & 3;

    __shared__ __align__(16) u64 sHTp[Sn * 2];   // [l*4+q] = H[q][l]
    __shared__ __align__(16) u64 sHR[4 * 17];    // hr[q*34+l] = H[q][l]
    __shared__ __align__(16) u64 sFR[Sn * 17];   // fr[j*34+l] = F[j][l]
    __shared__ __align__(16) u64 sPHT[4 * 17];   // pht[r*34+l]
    __shared__ __align__(16) float sZ[Sn * 4];   // whitened z rows
    __shared__ __align__(16) float sW[Sn * 4];   // W = F*Z rows
    __shared__ __align__(16) u64 sMu[16];
    __shared__ __align__(16) u64 sMp[16];
    __shared__ float sR16[16];
    __shared__ float sQf[32 * 33];               // Q acc-layout fragments
    __shared__ float sPu[Sn * PL];               // P plane (persistent)
    __shared__ float sXt[Sn * PL];               // Yt = F*P plane

    {
        float* frf = (float*)sFR;
        for (int idx = lane; idx < Sn * Sn; idx += 32) {
            int i = idx >> 5, l = idx & 31;
            frf[i * 34 + l] = Fm[idx];
        }
        float* hv  = (float*)sHTp;
        float* hrf = (float*)sHR;
        for (int idx = lane; idx < Mn * Sn; idx += 32) {
            int q = idx >> 5, l = idx & 31;
            float h = Hm[idx];
            hv [l * 4 + q]  = h;
            hrf[q * 34 + l] = h;
        }
        if (lane < 16) sR16[lane] = Rm[lane];
        for (int ti = 0; ti < 8; ++ti) {
            int mt = ti >> 2, nt = ti & 3;
#pragma unroll
            for (int j = 0; j < 4; ++j) {
                int row = mt * 16 + g + 8 * (j >> 1);
                int col = nt * 8 + 2 * tg + (j & 1);
                sQf[(ti * 4 + j) * 33 + lane] = Qm[row * Sn + col];
            }
        }
    }

    // ---- constant F A-fragments, hi+lo mask split ----
    uint32_t fh[8][4], fl[8][4];
#pragma unroll
    for (int mt = 0; mt < 2; ++mt)
#pragma unroll
        for (int kt = 0; kt < 4; ++kt) {
            int r0 = mt * 16 + g, c0 = kt * 8 + tg;
            float v[4];
            v[0] = Fm[r0 * Sn + c0];
            v[1] = Fm[(r0 + 8) * Sn + c0];
            v[2] = Fm[r0 * Sn + c0 + 4];
            v[3] = Fm[(r0 + 8) * Sn + c0 + 4];
#pragma unroll
            for (int j = 0; j < 4; ++j)
                split_tf32(v[j], fh[mt * 4 + kt][j], fl[mt * 4 + kt][j]);
        }

    // per-lane state + initial P plane
    float p[Sn];
#pragma unroll
    for (int i = 0; i < Sn; ++i) {
        p[i] = init_cov[(size_t)b * (Sn * Sn) + i * Sn + lane];
        sPu[i * PL + lane] = p[i];
    }
    float mloc = init_mean[b * Sn + lane];

    float* muF = (float*)sMu;
    float* mpF = (float*)sMp;
    mpF[lane] = mloc;
    __syncwarp();

    const float* yb = obs + (size_t)b * (Tn * Mn);
    float* out_means = out;
    float* out_covs  = out + (size_t)Tn * Bn * Mn;

    float4 yn = *(const float4*)yb;
    float* phtF = (float*)sPHT;

#pragma unroll 1
    for (int t = 0; t < Tn; ++t) {
        float4 yv = yn;
        int tnext = (t + 1 < Tn) ? (t + 1) : (Tn - 1);
        yn = *(const float4*)(yb + 4 * tnext);

        // ======== MMA1: Yt = F * P (independent of innovation) ========
        float yac[8][4];
#pragma unroll
        for (int ti = 0; ti < 8; ++ti)
#pragma unroll
            for (int j = 0; j < 4; ++j) yac[ti][j] = 0.f;
#pragma unroll
        for (int kt = 0; kt < 4; ++kt) {
#pragma unroll
            for (int nt = 0; nt < 4; ++nt) {
                float rb0 = sPu[(kt * 8 + tg) * PL + nt * 8 + g];
                float rb1 = sPu[(kt * 8 + tg + 4) * PL + nt * 8 + g];
                uint32_t bh0, bl0, bh1, bl1;
                split_tf32(rb0, bh0, bl0);
                split_tf32(rb1, bh1, bl1);
#pragma unroll
                for (int mt = 0; mt < 2; ++mt) {
                    mma_tf32(yac[mt * 4 + nt], fh[mt * 4 + kt], bh0, bh1);
                    mma_tf32(yac[mt * 4 + nt], fh[mt * 4 + kt], bl0, bl1);
                    mma_tf32(yac[mt * 4 + nt], fl[mt * 4 + kt], bh0, bh1);
                }
            }
        }
#pragma unroll
        for (int ti = 0; ti < 8; ++ti) {
            int mt = ti >> 2, nt = ti & 3;
            int rr = mt * 16 + g, cc = nt * 8 + 2 * tg;
            sXt[rr * PL + cc]           = yac[ti][0];
            sXt[rr * PL + cc + 1]       = yac[ti][1];
            sXt[(rr + 8) * PL + cc]     = yac[ti][2];
            sXt[(rr + 8) * PL + cc + 1] = yac[ti][3];
        }

        // ======== innovation (uses p registers = column of P) ========
        float mmv = 0.f;
        {
            u64 accm0 = 0ull, accm1 = 0ull;
            const u64* hq = &sHR[(lane & 3) * 17];
#pragma unroll
            for (int c = 0; c < 8; ++c) {
                accm0 = ffma2(hq[2 * c + 0], sMp[2 * c + 0], accm0);
                accm1 = ffma2(hq[2 * c + 1], sMp[2 * c + 1], accm1);
            }
            u64 accm = fadd2(accm0, accm1);
            float alo, ahi; unpack2(accm, alo, ahi);
            mmv = alo + ahi;
        }

        u64 a00 = 0ull, a01 = 0ull, a10 = 0ull, a11 = 0ull;
#pragma unroll
        for (int l = 0; l < Sn; l += 2) {
            ulonglong2 h0 = *(const ulonglong2*)&sHTp[l * 2];
            ulonglong2 h1 = *(const ulonglong2*)&sHTp[(l + 1) * 2];
            u64 ps0 = pack2(p[l], p[l]);
            u64 ps1 = pack2(p[l + 1], p[l + 1]);
            a00 = ffma2(ps0, h0.x, a00); a10 = ffma2(ps0, h0.y, a10);
            a01 = ffma2(ps1, h1.x, a01); a11 = ffma2(ps1, h1.y, a11);
        }
        u64 ph2a = fadd2(a00, a01);
        u64 ph2b = fadd2(a10, a11);
        float ph0, ph1, phh2, ph3;
        unpack2(ph2a, ph0, ph1);
        unpack2(ph2b, phh2, ph3);
        phtF[0 * 34 + lane] = ph0;
        phtF[1 * 34 + lane] = ph1;
        phtF[2 * 34 + lane] = phh2;
        phtF[3 * 34 + lane] = ph3;

        float c0 = __shfl_sync(0xffffffffu, mmv, 0);
        float c1 = __shfl_sync(0xffffffffu, mmv, 1);
        float c2 = __shfl_sync(0xffffffffu, mmv, 2);
        float c3 = __shfl_sync(0xffffffffu, mmv, 3);
        if (lane == 0)
            *(float4*)&out_means[((size_t)t * Bn + b) * 4] = make_float4(c0, c1, c2, c3);
        float r0 = yv.x - c0, r1 = yv.y - c1, r2 = yv.z - c2, r3 = yv.w - c3;
        __syncwarp();   // pht + sXt visible

        int q = (lane >> 2) & 3, r = lane & 3;
        float sv;
        {
            u64 acc0 = 0ull, acc1 = 0ull;
            const u64* hq = &sHR [q * 17];
            const u64* pr = &sPHT[r * 17];
#pragma unroll
            for (int c = 0; c < 8; ++c) {
                acc0 = ffma2(hq[2 * c + 0], pr[2 * c + 0], acc0);
                acc1 = ffma2(hq[2 * c + 1], pr[2 * c + 1], acc1);
            }
            u64 acc = fadd2(acc0, acc1);
            float alo, ahi; unpack2(acc, alo, ahi);
            sv = sR16[(q << 2) | r] + (alo + ahi);
        }
        if (lane < 16)
            out_covs[((size_t)t * Bn + b) * 16 + lane] = sv;

        if (t == Tn - 1) break;

        float s00 = __shfl_sync(0xffffffffu, sv, 0);
        float s10 = __shfl_sync(0xffffffffu, sv, 4);
        float s11 = __shfl_sync(0xffffffffu, sv, 5);
        float s20 = __shfl_sync(0xffffffffu, sv, 8);
        float s21 = __shfl_sync(0xffffffffu, sv, 9);
        float s22 = __shfl_sync(0xffffffffu, sv, 10);
        float s30 = __shfl_sync(0xffffffffu, sv, 12);
        float s31 = __shfl_sync(0xffffffffu, sv, 13);
        float s32 = __shfl_sync(0xffffffffu, sv, 14);
        float s33 = __shfl_sync(0xffffffffu, sv, 15);
        float i0 = rsqrtf(s00);
        float L10 = s10 * i0, L20 = s20 * i0, L30 = s30 * i0;
        float i1 = rsqrtf(s11 - L10 * L10);
        float L21 = (s21 - L20 * L10) * i1;
        float L31 = (s31 - L30 * L10) * i1;
        float i2 = rsqrtf(s22 - L20 * L20 - L21 * L21);
        float L32 = (s32 - L30 * L20 - L31 * L21) * i2;
        float i3 = rsqrtf(s33 - L30 * L30 - L31 * L31 - L32 * L32);

        // ---- whitened z (per-lane) and u = L^-1*resid (broadcast scalars):
        //      two INDEPENDENT forward solves; K_i.resid == z_i.u
        float z0 = ph0 * i0;
        float u0 = r0 * i0;
        float z1 = (ph1 - L10 * z0) * i1;
        float u1 = (r1 - L10 * u0) * i1;
        float z2 = (phh2 - L20 * z0 - L21 * z1) * i2;
        float u2 = (r2 - L20 * u0 - L21 * u1) * i2;
        float z3 = (ph3 - L30 * z0 - L31 * z1 - L32 * z2) * i3;
        float u3 = (r3 - L30 * u0 - L31 * u1 - L32 * u2) * i3;

        *(float4*)&sZ[lane * 4] = make_float4(z0, z1, z2, z3);
        __syncwarp();

        // mean update: m += z . u
        mloc = fmaf(z0, u0, fmaf(z1, u1, fmaf(z2, u2, fmaf(z3, u3, mloc))));
        muF[lane] = mloc;

        // ---- W = F * Z (per-lane row of W; Z rows in sZ) ----
        float w0 = 0.f, w1 = 0.f, w2 = 0.f, w3 = 0.f;
        {
            const u64* frw = &sFR[lane * 17];
#pragma unroll
            for (int c = 0; c < 16; ++c) {
                float f0, f1; unpack2(frw[c], f0, f1);
                float4 za = *(const float4*)&sZ[(2 * c) * 4];
                float4 zb = *(const float4*)&sZ[(2 * c + 1) * 4];
                w0 = fmaf(f0, za.x, w0); w1 = fmaf(f0, za.y, w1);
                w2 = fmaf(f0, za.z, w2); w3 = fmaf(f0, za.w, w3);
                w0 = fmaf(f1, zb.x, w0); w1 = fmaf(f1, zb.y, w1);
                w2 = fmaf(f1, zb.z, w2); w3 = fmaf(f1, zb.w, w3);
            }
        }
        *(float4*)&sW[lane * 4] = make_float4(w0, w1, w2, w3);
        __syncwarp();   // sW + sXt(all lanes) visible for MMA2/correction

        // ---- mean predict ----
        float mp;
        {
            u64 acc0 = 0ull, acc1 = 0ull;
            const u64* frw = &sFR[lane * 17];
#pragma unroll
            for (int c = 0; c < 8; ++c) {
                acc0 = ffma2(frw[2 * c + 0], sMu[2 * c + 0], acc0);
                acc1 = ffma2(frw[2 * c + 1], sMu[2 * c + 1], acc1);
            }
            u64 acc = fadd2(acc0, acc1);
            float alo, ahi; unpack2(acc, alo, ahi);
            mp = alo + ahi;
        }

        // ======== MMA2: P' = F * Y + Q, Y[k][n] = Yt[n][k] ========
        float pac[8][4];
#pragma unroll
        for (int ti = 0; ti < 8; ++ti)
#pragma unroll
            for (int j = 0; j < 4; ++j)
                pac[ti][j] = sQf[(ti * 4 + j) * 33 + lane];
#pragma unroll
        for (int kt = 0; kt < 4; ++kt) {
#pragma unroll
            for (int nt = 0; nt < 4; ++nt) {
                float rb0 = sXt[(nt * 8 + g) * PL + kt * 8 + tg];
                float rb1 = sXt[(nt * 8 + g) * PL + kt * 8 + tg + 4];
                uint32_t bh0, bl0, bh1, bl1;
                split_tf32(rb0, bh0, bl0);
                split_tf32(rb1, bh1, bl1);
#pragma unroll
                for (int mt = 0; mt < 2; ++mt) {
                    mma_tf32(pac[mt * 4 + nt], fh[mt * 4 + kt], bh0, bh1);
                    mma_tf32(pac[mt * 4 + nt], fh[mt * 4 + kt], bl0, bl1);
                    mma_tf32(pac[mt * 4 + nt], fl[mt * 4 + kt], bh0, bh1);
                }
            }
        }

        // ---- rank-4 correction on fragments: pac -= W_row . W_col ----
#pragma unroll
        for (int ti = 0; ti < 8; ++ti) {
            int mt = ti >> 2, nt = ti & 3;
            int rr = mt * 16 + g, cc = nt * 8 + 2 * tg;
            float4 wr0 = *(const float4*)&sW[rr * 4];
            float4 wr1 = *(const float4*)&sW[(rr + 8) * 4];
            float4 wc0 = *(const float4*)&sW[cc * 4];
            float4 wc1 = *(const float4*)&sW[(cc + 1) * 4];
            float d00 = wr0.x * wc0.x; d00 = fmaf(wr0.y, wc0.y, d00);
            d00 = fmaf(wr0.z, wc0.z, d00); d00 = fmaf(wr0.w, wc0.w, d00);
            float d01 = wr0.x * wc1.x; d01 = fmaf(wr0.y, wc1.y, d01);
            d01 = fmaf(wr0.z, wc1.z, d01); d01 = fmaf(wr0.w, wc1.w, d01);
            float d10 = wr1.x * wc0.x; d10 = fmaf(wr1.y, wc0.y, d10);
            d10 = fmaf(wr1.z, wc0.z, d10); d10 = fmaf(wr1.w, wc0.w, d10);
            float d11 = wr1.x * wc1.x; d11 = fmaf(wr1.y, wc1.y, d11);
            d11 = fmaf(wr1.z, wc1.z, d11); d11 = fmaf(wr1.w, wc1.w, d11);
            pac[ti][0] -= d00;
            pac[ti][1] -= d01;
            pac[ti][2] -= d10;
            pac[ti][3] -= d11;
        }

        // store P' plane
#pragma unroll
        for (int ti = 0; ti < 8; ++ti) {
            int mt = ti >> 2, nt = ti & 3;
            int rr = mt * 16 + g, cc = nt * 8 + 2 * tg;
            sPu[rr * PL + cc]           = pac[ti][0];
            sPu[rr * PL + cc + 1]       = pac[ti][1];
            sPu[(rr + 8) * PL + cc]     = pac[ti][2];
            sPu[(rr + 8) * PL + cc + 1] = pac[ti][3];
        }

        mloc = mp;
        mpF[lane] = mp;
        __syncwarp();

        // reload per-lane column of P'
#pragma unroll
        for (int i = 0; i < Sn; ++i)
            p[i] = sPu[i * PL + lane];
    }
}

extern "C" void kernel_launch(void* const* d_in, const int* in_sizes, int n_in,
                              void* d_out, int out_size)
{
    const float* obs       = (const float*)d_in[0];
    const float* Fm        = (const float*)d_in[1];
    const float* Qm        = (const float*)d_in[2];
    const float* Hm        = (const float*)d_in[3];
    const float* Rm        = (const float*)d_in[4];
    const float* init_mean = (const float*)d_in[5];
    const float* init_cov  = (const float*)d_in[6];
    float* out = (float*)d_out;

    kalman_kernel<<<Bn, 32>>>(obs, Fm, Qm, Hm, Rm, init_mean, init_cov, out);
}